// round 4
// baseline (speedup 1.0000x reference)
#include <cuda_runtime.h>

#define D 128
#define NMAX 50176
#define EMAX 800000
#define N_LAYERS 4

// Scratch (device globals: allocation-free rule)
__device__ int   g_deg_out[NMAX];
__device__ int   g_deg_in[NMAX];
__device__ float g_norm_src[NMAX];
__device__ float g_norm_dst[NMAX];
__device__ int   g_row_ptr[NMAX + 1];
__device__ int   g_cursor[NMAX];
__device__ int   g_col[EMAX];
__device__ __align__(16) float g_h0[NMAX * D];
__device__ __align__(16) float g_h1[NMAX * D];
__device__ __align__(16) float g_agg[NMAX * D];

__global__ void k_zero_deg(int n) {
    int i = blockIdx.x * blockDim.x + threadIdx.x;
    if (i < n) { g_deg_out[i] = 0; g_deg_in[i] = 0; }
}

__global__ void k_count(const int* __restrict__ src,
                        const int* __restrict__ dst, int e) {
    int i = blockIdx.x * blockDim.x + threadIdx.x;
    if (i < e) {
        atomicAdd(&g_deg_out[src[i]], 1);
        atomicAdd(&g_deg_in[dst[i]], 1);
    }
}

__global__ void k_norm(int n) {
    int i = blockIdx.x * blockDim.x + threadIdx.x;
    if (i < n) {
        g_norm_src[i] = rsqrtf(fmaxf((float)g_deg_out[i], 1.0f));
        g_norm_dst[i] = rsqrtf(fmaxf((float)g_deg_in[i], 1.0f));
    }
}

// Single-block exclusive scan of g_deg_in -> g_row_ptr / g_cursor
__global__ void k_scan(int n) {
    __shared__ int sh[1024];
    __shared__ int run;
    int t = threadIdx.x;
    if (t == 0) run = 0;
    __syncthreads();
    for (int base = 0; base < n; base += 1024) {
        int i = base + t;
        int v = (i < n) ? g_deg_in[i] : 0;
        sh[t] = v;
        __syncthreads();
        #pragma unroll
        for (int off = 1; off < 1024; off <<= 1) {
            int add = (t >= off) ? sh[t - off] : 0;
            __syncthreads();
            sh[t] += add;
            __syncthreads();
        }
        int excl = sh[t] - v + run;            // run read before t0 updates it
        if (i < n) { g_row_ptr[i] = excl; g_cursor[i] = excl; }
        __syncthreads();
        if (t == 0) run += sh[1023];
        __syncthreads();
    }
    if (threadIdx.x == 0) g_row_ptr[n] = run;
}

__global__ void k_fill(const int* __restrict__ src,
                       const int* __restrict__ dst, int e) {
    int i = blockIdx.x * blockDim.x + threadIdx.x;
    if (i < e) {
        int p = atomicAdd(&g_cursor[dst[i]], 1);
        g_col[p] = src[i];
    }
}

// Aggregation: one warp per destination node, lane = one float4 (4 of 128 dims)
// agg[i] = norm_dst[i] * sum_{s in in(i)} norm_src[s] * h[s]
__global__ void k_agg(const float* __restrict__ hin, float* __restrict__ agg, int n) {
    int w    = (blockIdx.x * blockDim.x + threadIdx.x) >> 5;
    int lane = threadIdx.x & 31;
    if (w >= n) return;
    int j0 = g_row_ptr[w];
    int j1 = g_row_ptr[w + 1];
    const float4* h4 = (const float4*)hin;
    float4 acc = make_float4(0.f, 0.f, 0.f, 0.f);
    for (int j = j0; j < j1; j++) {
        int s = g_col[j];
        float ns = g_norm_src[s];
        float4 v = __ldg(&h4[(size_t)s * 32 + lane]);
        acc.x = fmaf(ns, v.x, acc.x);
        acc.y = fmaf(ns, v.y, acc.y);
        acc.z = fmaf(ns, v.z, acc.z);
        acc.w = fmaf(ns, v.w, acc.w);
    }
    float nd = g_norm_dst[w];
    float4 o = make_float4(acc.x * nd, acc.y * nd, acc.z * nd, acc.w * nd);
    ((float4*)agg)[(size_t)w * 32 + lane] = o;
}

// C[n,128] = A[n,128] @ Wl[128,128] + bl[128]
// Block tile 64(M) x 128(N full), K chunked by 32. 256 threads, 8x4 micro-tile.
__global__ void k_gemm(const float* __restrict__ A, const float* __restrict__ Wl,
                       const float* __restrict__ bl, float* __restrict__ C, int n) {
    __shared__ __align__(16) float As[32][68];   // transposed A chunk, padded row
    __shared__ float4 Ws[32][32];                // W chunk [k][n/4]
    int tid = threadIdx.x;
    int tx = tid & 31;       // n4 index: cols tx*4 .. tx*4+3
    int ty = tid >> 5;       // m group: rows ty*8 .. ty*8+7
    int m0 = blockIdx.x * 64;
    float acc[8][4] = {};
    const float4* W4 = (const float4*)Wl;

    for (int kc = 0; kc < 128; kc += 32) {
        // A tile: rows m0..m0+63, cols kc..kc+31 -> As[k][m] (transposed)
        #pragma unroll
        for (int it = 0; it < 2; it++) {
            int m = (tid >> 3) + it * 32;
            int c4 = tid & 7;
            int row = m0 + m;
            float4 v = make_float4(0.f, 0.f, 0.f, 0.f);
            if (row < n) v = *(const float4*)&A[(size_t)row * 128 + kc + c4 * 4];
            As[c4 * 4 + 0][m] = v.x;
            As[c4 * 4 + 1][m] = v.y;
            As[c4 * 4 + 2][m] = v.z;
            As[c4 * 4 + 3][m] = v.w;
        }
        // W chunk: 32 k-rows x 128 cols = 1024 float4
        #pragma unroll
        for (int it = 0; it < 4; it++) {
            int idx = tid + it * 256;
            int k  = idx >> 5;
            int n4 = idx & 31;
            Ws[k][n4] = W4[(size_t)(kc + k) * 32 + n4];
        }
        __syncthreads();
        #pragma unroll
        for (int k = 0; k < 32; k++) {
            float4 w  = Ws[k][tx];
            float4 a0 = *(const float4*)&As[k][ty * 8];
            float4 a1 = *(const float4*)&As[k][ty * 8 + 4];
            float av[8] = {a0.x, a0.y, a0.z, a0.w, a1.x, a1.y, a1.z, a1.w};
            #pragma unroll
            for (int i = 0; i < 8; i++) {
                acc[i][0] = fmaf(av[i], w.x, acc[i][0]);
                acc[i][1] = fmaf(av[i], w.y, acc[i][1]);
                acc[i][2] = fmaf(av[i], w.z, acc[i][2]);
                acc[i][3] = fmaf(av[i], w.w, acc[i][3]);
            }
        }
        __syncthreads();
    }

    float4 bb = ((const float4*)bl)[tx];
    #pragma unroll
    for (int i = 0; i < 8; i++) {
        int row = m0 + ty * 8 + i;
        if (row < n) {
            float4 o = make_float4(acc[i][0] + bb.x, acc[i][1] + bb.y,
                                   acc[i][2] + bb.z, acc[i][3] + bb.w);
            ((float4*)C)[(size_t)row * 32 + tx] = o;
        }
    }
}

extern "C" void kernel_launch(void* const* d_in, const int* in_sizes, int n_in,
                              void* d_out, int out_size) {
    const float* feat = (const float*)d_in[0];
    const float* W    = (const float*)d_in[1];
    const float* b    = (const float*)d_in[2];
    const int*   src  = (const int*)d_in[3];   // jax default: int64 request -> int32 arrays
    const int*   dst  = (const int*)d_in[4];
    int N = in_sizes[0] / D;
    int E = in_sizes[3];

    float *h0, *h1, *agg;
    cudaGetSymbolAddress((void**)&h0,  g_h0);
    cudaGetSymbolAddress((void**)&h1,  g_h1);
    cudaGetSymbolAddress((void**)&agg, g_agg);

    int nb = (N + 255) / 256;
    int eb = (E + 255) / 256;

    // Setup: degrees, norms, CSR by dst
    k_zero_deg<<<nb, 256>>>(N);
    k_count<<<eb, 256>>>(src, dst, E);
    k_norm<<<nb, 256>>>(N);
    k_scan<<<1, 1024>>>(N);
    k_fill<<<eb, 256>>>(src, dst, E);

    float* out = (float*)d_out;
    const float* hin = feat;
    int aggBlocks  = (N + 7) / 8;       // 8 warps per block, warp per node
    int gemmBlocks = (N + 63) / 64;

    for (int l = 0; l < N_LAYERS; l++) {
        k_agg<<<aggBlocks, 256>>>(hin, agg, N);
        float* hout = (l == N_LAYERS - 1) ? out : ((l & 1) ? h1 : h0);
        k_gemm<<<gemmBlocks, 256>>>(agg, W + (size_t)l * D * D, b + (size_t)l * D, hout, N);
        hin = hout;
    }
}